// round 5
// baseline (speedup 1.0000x reference)
#include <cuda_runtime.h>
#include <cuda_bf16.h>
#include <cstdint>
#include <cstddef>

constexpr int S_BS = 8, S_SEQ = 512, S_DIM = 768, S_NP = 32, S_PE = 200;
constexpr int S_L = 20, S_EMB = 128, S_VOCAB = 30522;
constexpr int S_BP = S_BS * S_NP;            // 256
constexpr int S_ROWS = S_BP * S_L;           // 5120
constexpr int S_DIN2 = 2 * S_DIM;            // 1536

// ---------------- scratch ----------------
constexpr size_t SZ_A1   = (size_t)S_BP * S_DIN2 * 2;      // bf16
constexpr size_t SZ_W1T  = (size_t)S_DIM * S_DIN2 * 2;
constexpr size_t SZ_W2T  = (size_t)S_DIM * S_DIM * 2;
constexpr size_t SZ_WPT  = (size_t)S_EMB * S_DIM * 2;
constexpr size_t SZ_WD   = (size_t)S_VOCAB * S_EMB * 2;
constexpr size_t SZ_P    = (size_t)S_BP * S_DIM * 4;       // f32
constexpr size_t SZ_POSP = (size_t)S_L * S_DIM * 4;
constexpr size_t SZ_H1   = (size_t)S_ROWS * S_DIM * 2;
constexpr size_t SZ_PRE2 = (size_t)S_ROWS * S_DIM * 4;
constexpr size_t SZ_H3   = (size_t)S_ROWS * S_EMB * 2;

constexpr size_t OFF_A1H  = 0;
constexpr size_t OFF_A1L  = OFF_A1H  + SZ_A1;
constexpr size_t OFF_W1TH = OFF_A1L  + SZ_A1;
constexpr size_t OFF_W1TL = OFF_W1TH + SZ_W1T;
constexpr size_t OFF_W2TH = OFF_W1TL + SZ_W1T;
constexpr size_t OFF_W2TL = OFF_W2TH + SZ_W2T;
constexpr size_t OFF_WPTH = OFF_W2TL + SZ_W2T;
constexpr size_t OFF_WPTL = OFF_WPTH + SZ_WPT;
constexpr size_t OFF_WDH  = OFF_WPTL + SZ_WPT;
constexpr size_t OFF_WDL  = OFF_WDH  + SZ_WD;
constexpr size_t OFF_P    = OFF_WDL  + SZ_WD;
constexpr size_t OFF_POSP = OFF_P    + SZ_P;
constexpr size_t OFF_H1H  = OFF_POSP + SZ_POSP;
constexpr size_t OFF_H1L  = OFF_H1H  + SZ_H1;
constexpr size_t OFF_PRE2 = OFF_H1L  + SZ_H1;
constexpr size_t OFF_H2H  = OFF_PRE2 + SZ_PRE2;
constexpr size_t OFF_H2L  = OFF_H2H  + SZ_H1;
constexpr size_t OFF_H3H  = OFF_H2L  + SZ_H1;
constexpr size_t OFF_H3L  = OFF_H3H  + SZ_H3;
constexpr size_t SCRATCH_BYTES = OFF_H3L + SZ_H3;

__device__ __align__(1024) unsigned char g_scratch[SCRATCH_BYTES];

// ---------------- helpers ----------------
__device__ __forceinline__ void split2(float v, __nv_bfloat16& hi, __nv_bfloat16& lo) {
    __nv_bfloat16 h = __float2bfloat16(v);
    hi = h;
    lo = __float2bfloat16(v - __bfloat162float(h));
}

__device__ __forceinline__ float gelu_exact(float x) {
    return 0.5f * x * (1.0f + erff(x * 0.70710678118654752440f));
}

__device__ __forceinline__ uint32_t sm_u32(const void* p) {
    uint32_t a;
    asm("{ .reg .u64 t; cvta.to.shared.u64 t, %1; cvt.u32.u64 %0, t; }"
        : "=r"(a) : "l"(p));
    return a;
}

#define MMA_BF16(c, a, b)                                                     \
    asm volatile(                                                             \
        "mma.sync.aligned.m16n8k16.row.col.f32.bf16.bf16.f32 "                \
        "{%0,%1,%2,%3},{%4,%5,%6,%7},{%8,%9},{%0,%1,%2,%3};\n"                \
        : "+f"((c)[0]), "+f"((c)[1]), "+f"((c)[2]), "+f"((c)[3])              \
        : "r"((a)[0]), "r"((a)[1]), "r"((a)[2]), "r"((a)[3]),                 \
          "r"((b)[0]), "r"((b)[1]))

#define LDSM4(r, a)                                                           \
    asm volatile("ldmatrix.sync.aligned.m8n8.x4.shared.b16 "                  \
                 "{%0,%1,%2,%3}, [%4];"                                       \
                 : "=r"((r)[0]), "=r"((r)[1]), "=r"((r)[2]), "=r"((r)[3])     \
                 : "r"(a))

#define CP16(dst, src, sz)                                                    \
    asm volatile("cp.async.cg.shared.global [%0], [%1], 16, %2;\n"            \
                 :: "r"(dst), "l"(src), "r"(sz))

#define CP_COMMIT()  asm volatile("cp.async.commit_group;\n" ::: "memory")
#define CP_WAIT(n)   asm volatile("cp.async.wait_group %0;\n" :: "n"(n) : "memory")

__device__ __forceinline__ uint32_t swz(uint32_t off) {
    return off ^ ((off >> 3) & 0x70);
}

// ---------------- fused prep kernel ----------------
__device__ void do_transpose32(const float* __restrict__ W, int K, int N,
                               __nv_bfloat16* __restrict__ Th,
                               __nv_bfloat16* __restrict__ Tl,
                               int tilex, int tiley) {
    __shared__ float tile[32][33];
    int t = threadIdx.x;
    int x = t & 31, y = t >> 5;
    int k0 = tiley * 32, n0 = tilex * 32;
    #pragma unroll
    for (int i = 0; i < 4; i++) {
        int kk = y + i * 8;
        tile[kk][x] = W[(size_t)(k0 + kk) * N + n0 + x];
    }
    __syncthreads();
    #pragma unroll
    for (int i = 0; i < 4; i++) {
        int nn = y + i * 8;
        float v = tile[x][nn];
        size_t o = (size_t)(n0 + nn) * K + k0 + x;
        split2(v, Th[o], Tl[o]);
    }
}

constexpr int PB_GA = (S_BP * S_DIN2) / 256;                 // 1536 gather blocks
constexpr int PB_W1 = PB_GA + (S_DIM / 32) * (S_DIN2 / 32);  // +1152 = 2688
constexpr int PB_W2 = PB_W1 + (S_DIM / 32) * (S_DIM / 32);   // +576  = 3264
constexpr int PB_WP = PB_W2 + (S_EMB / 32) * (S_DIM / 32);   // +96   = 3360
constexpr int WD_ELEMS = S_VOCAB * S_EMB;                     // 3906816
constexpr int PB_WD = PB_WP + (WD_ELEMS + 1023) / 1024;       // +3816 = 7176
constexpr int PB_POS = PB_WD + S_L;                           // +20   = 7196

__global__ void prep_all_kernel(const float* __restrict__ hidden,
                                const int* __restrict__ pairs,
                                const float* __restrict__ pos_emb,
                                const float* __restrict__ W1,
                                const float* __restrict__ W2,
                                const float* __restrict__ Wp,
                                const float* __restrict__ Wdec,
                                __nv_bfloat16* __restrict__ A1h, __nv_bfloat16* __restrict__ A1l,
                                __nv_bfloat16* __restrict__ W1th, __nv_bfloat16* __restrict__ W1tl,
                                __nv_bfloat16* __restrict__ W2th, __nv_bfloat16* __restrict__ W2tl,
                                __nv_bfloat16* __restrict__ Wpth, __nv_bfloat16* __restrict__ Wptl,
                                __nv_bfloat16* __restrict__ Wdh,  __nv_bfloat16* __restrict__ Wdl,
                                float* __restrict__ PosP) {
    int bx = blockIdx.x;
    int tid = threadIdx.x;
    if (bx < PB_GA) {
        int id = bx * 256 + tid;
        int bp = id / S_DIN2;
        int k  = id - bp * S_DIN2;
        int side = (k >= S_DIM) ? 1 : 0;
        int col  = k - side * S_DIM;
        int s = pairs[bp * 2 + side];
        int b = bp >> 5;
        float v = hidden[((size_t)(b * S_SEQ + s)) * S_DIM + col];
        split2(v, A1h[id], A1l[id]);
    } else if (bx < PB_W1) {
        int b = bx - PB_GA;
        do_transpose32(W1, S_DIN2, S_DIM, W1th, W1tl,
                       b % (S_DIM / 32), b / (S_DIM / 32));
    } else if (bx < PB_W2) {
        int b = bx - PB_W1;
        do_transpose32(W2, S_DIM, S_DIM, W2th, W2tl,
                       b % (S_DIM / 32), b / (S_DIM / 32));
    } else if (bx < PB_WP) {
        int b = bx - PB_W2;
        do_transpose32(Wp, S_DIM, S_EMB, Wpth, Wptl,
                       b % (S_EMB / 32), b / (S_EMB / 32));
    } else if (bx < PB_WD) {
        int base = (bx - PB_WP) * 1024;
        #pragma unroll
        for (int u = 0; u < 4; u++) {
            int id = base + tid + u * 256;
            if (id < WD_ELEMS) split2(Wdec[id], Wdh[id], Wdl[id]);
        }
    } else {
        int l = bx - PB_WD;
        __shared__ float sp[S_PE];
        if (tid < S_PE) sp[tid] = pos_emb[l * S_PE + tid];
        __syncthreads();
        #pragma unroll
        for (int j = 0; j < 3; j++) {
            int n = tid + j * 256;
            float a = 0.f;
            #pragma unroll 4
            for (int k = 0; k < S_PE; k++)
                a += sp[k] * W1[(size_t)(S_DIN2 + k) * S_DIM + n];
            PosP[l * S_DIM + n] = a;
        }
    }
}

// ---------------- ldmatrix + mma compute for one 64-k chunk ----------------
// smem matrices: [row][128B] rows with SW128 swizzle.
// Term-major MMA ordering: 16 independent accs between dependent updates.
template<int MI>
__device__ __forceinline__ void chunk_mma(uint32_t sAh, uint32_t sAl,
                                          uint32_t sBh, uint32_t sBl,
                                          int m0, int n0, int lane,
                                          float acc[][4][4]) {
    #pragma unroll
    for (int ks = 0; ks < 4; ks++) {
        uint32_t ah[MI][4], al[MI][4], bh[8], bl[8];
        #pragma unroll
        for (int mi = 0; mi < MI; mi++) {
            int row = m0 + mi * 16 + (lane & 15);
            int c16 = ks * 2 + (lane >> 4);
            uint32_t off = swz((uint32_t)(row * 128 + c16 * 16));
            LDSM4(ah[mi], sAh + off);
            LDSM4(al[mi], sAl + off);
        }
        #pragma unroll
        for (int np = 0; np < 2; np++) {
            int row = n0 + np * 16 + ((lane >> 4) << 3) + (lane & 7);
            int c16 = ks * 2 + ((lane >> 3) & 1);
            uint32_t off = swz((uint32_t)(row * 128 + c16 * 16));
            LDSM4(&bh[np * 4], sBh + off);
            LDSM4(&bl[np * 4], sBl + off);
        }
        #pragma unroll
        for (int mi = 0; mi < MI; mi++)
            #pragma unroll
            for (int nj = 0; nj < 4; nj++)
                MMA_BF16(acc[mi][nj], ah[mi], &bh[nj * 2]);
        #pragma unroll
        for (int mi = 0; mi < MI; mi++)
            #pragma unroll
            for (int nj = 0; nj < 4; nj++)
                MMA_BF16(acc[mi][nj], ah[mi], &bl[nj * 2]);
        #pragma unroll
        for (int mi = 0; mi < MI; mi++)
            #pragma unroll
            for (int nj = 0; nj < 4; nj++)
                MMA_BF16(acc[mi][nj], al[mi], &bh[nj * 2]);
    }
}

// ---------------- k-loop GEMM: C[M,N] = A[M,K] @ Bt[N,K]^T (+bias) ----------
template<int MI>
__global__ void __launch_bounds__(256)
gemm_kl(int M, int N, int K,
        const __nv_bfloat16* __restrict__ Ahp, const __nv_bfloat16* __restrict__ Alp,
        const __nv_bfloat16* __restrict__ Bhp, const __nv_bfloat16* __restrict__ Blp,
        const float* __restrict__ bias,
        float* __restrict__ Cf,
        __nv_bfloat16* __restrict__ Ch, __nv_bfloat16* __restrict__ Cl) {
    constexpr int MT = MI * 32;
    constexpr int AB = MT * 128;            // bytes per A matrix per stage
    constexpr int SS = 2 * AB + 32768;      // stage bytes
    extern __shared__ __align__(1024) unsigned char smraw[];
    const uint32_t smb = sm_u32(smraw);
    const int tid = threadIdx.x, lane = tid & 31, warp = tid >> 5;
    const int m0 = (warp >> 2) * MI * 16, n0 = (warp & 3) * 32;
    const int am0 = blockIdx.x * MT, bn0 = blockIdx.y * 128;
    const long rowB = (long)K * 2;
    const int nch = K >> 6;

    float acc[MI][4][4];
    #pragma unroll
    for (int a = 0; a < MI; a++)
        #pragma unroll
        for (int b = 0; b < 4; b++)
            #pragma unroll
            for (int c = 0; c < 4; c++) acc[a][b][c] = 0.f;

    auto load_stage = [&](int c, int s) {
        const uint32_t sb = smb + (uint32_t)s * SS;
        constexpr int AU = AB / 16;
        #pragma unroll
        for (int i = 0; i < (2 * AU) / 256; i++) {
            int u = tid + i * 256;
            int hi = (u >= AU); int v = u - hi * AU;
            int row = v >> 3, j = v & 7;
            uint32_t off = swz((uint32_t)(row * 128 + j * 16));
            const char* src = (hi ? (const char*)Alp : (const char*)Ahp)
                              + (long)(am0 + row) * rowB + (long)c * 128 + j * 16;
            CP16(sb + (uint32_t)hi * AB + off, src, 16);
        }
        #pragma unroll
        for (int i = 0; i < 8; i++) {
            int u = tid + i * 256;
            int hi = (u >= 1024); int v = u - hi * 1024;
            int row = v >> 3, j = v & 7;
            int grow = bn0 + row;
            int ok = (grow < N) ? 16 : 0;
            uint32_t off = swz((uint32_t)(row * 128 + j * 16));
            const char* src = (hi ? (const char*)Blp : (const char*)Bhp)
                              + (long)(ok ? grow : 0) * rowB + (long)c * 128 + j * 16;
            CP16(sb + 2u * AB + (uint32_t)hi * 16384u + off, src, ok);
        }
        CP_COMMIT();
    };

    load_stage(0, 0);
    for (int c = 0; c < nch; c++) {
        int s = c & 1;
        if (c + 1 < nch) { load_stage(c + 1, s ^ 1); CP_WAIT(1); }
        else             { CP_WAIT(0); }
        __syncthreads();
        uint32_t sb = smb + (uint32_t)s * SS;
        chunk_mma<MI>(sb, sb + AB, sb + 2 * AB, sb + 2 * AB + 16384,
                      m0, n0, lane, acc);
        __syncthreads();
    }

    const int g = lane >> 2, tg = lane & 3;
    #pragma unroll
    for (int mi = 0; mi < MI; mi++) {
        int r0 = am0 + m0 + mi * 16 + g;
        size_t base0 = (size_t)r0 * N;
        size_t base1 = (size_t)(r0 + 8) * N;
        #pragma unroll
        for (int nj = 0; nj < 4; nj++) {
            int c0 = bn0 + n0 + nj * 8 + tg * 2;
            float v0 = acc[mi][nj][0], v1 = acc[mi][nj][1];
            float v2 = acc[mi][nj][2], v3 = acc[mi][nj][3];
            if (bias) {
                float bb0 = bias[c0], bb1 = bias[c0 + 1];
                v0 += bb0; v1 += bb1; v2 += bb0; v3 += bb1;
            }
            if (Cf) {
                *(float2*)(Cf + base0 + c0) = make_float2(v0, v1);
                *(float2*)(Cf + base1 + c0) = make_float2(v2, v3);
            } else {
                split2(v0, Ch[base0 + c0],     Cl[base0 + c0]);
                split2(v1, Ch[base0 + c0 + 1], Cl[base0 + c0 + 1]);
                split2(v2, Ch[base1 + c0],     Cl[base1 + c0]);
                split2(v3, Ch[base1 + c0 + 1], Cl[base1 + c0 + 1]);
            }
        }
    }
}

// ---------------- persistent n-loop GEMM for GEMM4 (K=128 fixed) -----------
constexpr int NL_SMEM = 196608;

__global__ void __launch_bounds__(256)
gemm_nl(int M, int N,
        const __nv_bfloat16* __restrict__ Ahp, const __nv_bfloat16* __restrict__ Alp,
        const __nv_bfloat16* __restrict__ Bhp, const __nv_bfloat16* __restrict__ Blp,
        float* __restrict__ Cf) {
    extern __shared__ __align__(1024) unsigned char smraw[];
    const uint32_t smb = sm_u32(smraw);
    const int tid = threadIdx.x, lane = tid & 31, warp = tid >> 5;
    const int m0 = (warp >> 2) * 64, n0 = (warp & 3) * 32;
    const int ntiles = (N + 127) >> 7;
    const int W = (M >> 7) * ntiles;
    const int Q = W / gridDim.x, R = W % gridDim.x;
    const int k = blockIdx.x;
    const int beg = k * Q + min(k, R);
    const int cnt = Q + (k < R ? 1 : 0);
    if (cnt == 0) return;

    auto load_A = [&](int m) {
        #pragma unroll
        for (int i = 0; i < 16; i++) {
            int u = tid + i * 256;            // [0,4096)
            int c = u >> 11; int v = u & 2047;
            int hi = v >> 10; int v2 = v & 1023;
            int row = v2 >> 3, j = v2 & 7;
            uint32_t off = swz((uint32_t)(row * 128 + j * 16));
            const char* src = (hi ? (const char*)Alp : (const char*)Ahp)
                              + (long)(m * 128 + row) * 256 + c * 128 + j * 16;
            CP16(smb + (uint32_t)c * 32768u + (uint32_t)hi * 16384u + off, src, 16);
        }
        CP_COMMIT();
    };
    auto load_B = [&](int n, int s) {
        #pragma unroll
        for (int i = 0; i < 16; i++) {
            int u = tid + i * 256;
            int c = u >> 11; int v = u & 2047;
            int hi = v >> 10; int v2 = v & 1023;
            int row = v2 >> 3, j = v2 & 7;
            int grow = n * 128 + row;
            int ok = (grow < N) ? 16 : 0;
            uint32_t off = swz((uint32_t)(row * 128 + j * 16));
            const char* src = (hi ? (const char*)Blp : (const char*)Bhp)
                              + (long)(ok ? grow : 0) * 256 + c * 128 + j * 16;
            CP16(smb + 65536u + (uint32_t)s * 65536u
                 + (uint32_t)c * 32768u + (uint32_t)hi * 16384u + off, src, ok);
        }
        CP_COMMIT();
    };

    int loadedm = beg / ntiles;
    load_A(loadedm);
    load_B(beg % ntiles, 0);

    const int g = lane >> 2, tg = lane & 3;
    for (int it = 0; it < cnt; it++) {
        int w = beg + it, s = it & 1;
        int mm = w / ntiles, nn = w % ntiles;
        if (mm != loadedm) { load_A(mm); loadedm = mm; }
        if (it + 1 < cnt) {
            int wn = w + 1;
            load_B(wn % ntiles, s ^ 1);
            CP_WAIT(1);
        } else {
            CP_WAIT(0);
        }
        __syncthreads();

        float acc[4][4][4];
        #pragma unroll
        for (int a = 0; a < 4; a++)
            #pragma unroll
            for (int b = 0; b < 4; b++)
                #pragma unroll
                for (int c = 0; c < 4; c++) acc[a][b][c] = 0.f;

        uint32_t bB = smb + 65536u + (uint32_t)s * 65536u;
        #pragma unroll
        for (int c = 0; c < 2; c++) {
            uint32_t aoff = smb + (uint32_t)c * 32768u;
            uint32_t boff = bB + (uint32_t)c * 32768u;
            chunk_mma<4>(aoff, aoff + 16384u, boff, boff + 16384u,
                         m0, n0, lane, acc);
        }

        #pragma unroll
        for (int mi = 0; mi < 4; mi++) {
            int r0 = mm * 128 + m0 + mi * 16 + g;
            size_t base0 = (size_t)r0 * N;
            size_t base1 = (size_t)(r0 + 8) * N;
            #pragma unroll
            for (int nj = 0; nj < 4; nj++) {
                int c0 = nn * 128 + n0 + nj * 8 + tg * 2;
                if (c0 + 1 < N) {
                    *(float2*)(Cf + base0 + c0) =
                        make_float2(acc[mi][nj][0], acc[mi][nj][1]);
                    *(float2*)(Cf + base1 + c0) =
                        make_float2(acc[mi][nj][2], acc[mi][nj][3]);
                } else if (c0 < N) {
                    Cf[base0 + c0] = acc[mi][nj][0];
                    Cf[base1 + c0] = acc[mi][nj][2];
                }
            }
        }
        __syncthreads();
    }
}

// ---------------- gelu + LN (one 768-row per 256-thread block) ----------------
__device__ __forceinline__ void ln_write(float v0, float v1, float v2, int r,
                                         const float* __restrict__ gam,
                                         const float* __restrict__ bet,
                                         __nv_bfloat16* __restrict__ Hh,
                                         __nv_bfloat16* __restrict__ Hl,
                                         float* red) {
    int t = threadIdx.x;
    float s1 = v0 + v1 + v2;
    float s2 = v0 * v0 + v1 * v1 + v2 * v2;
    #pragma unroll
    for (int o = 16; o; o >>= 1) {
        s1 += __shfl_xor_sync(0xffffffffu, s1, o);
        s2 += __shfl_xor_sync(0xffffffffu, s2, o);
    }
    if ((t & 31) == 0) { red[t >> 5] = s1; red[8 + (t >> 5)] = s2; }
    __syncthreads();
    s1 = 0.f; s2 = 0.f;
    #pragma unroll
    for (int i = 0; i < 8; i++) { s1 += red[i]; s2 += red[8 + i]; }
    float mean = s1 * (1.0f / S_DIM);
    float var  = s2 * (1.0f / S_DIM) - mean * mean;
    float rstd = rsqrtf(fmaxf(var, 0.0f) + 1e-12f);
    size_t rb = (size_t)r * S_DIM;
    float v[3] = {v0, v1, v2};
    #pragma unroll
    for (int j = 0; j < 3; j++) {
        int c = t + j * 256;
        float y = (v[j] - mean) * rstd * gam[c] + bet[c];
        split2(y, Hh[rb + c], Hl[rb + c]);
    }
}

__global__ void expand_act_kernel(const float* __restrict__ P,
                                  const float* __restrict__ PosP,
                                  const float* __restrict__ b1,
                                  const float* __restrict__ g1,
                                  const float* __restrict__ be1,
                                  __nv_bfloat16* __restrict__ Hh,
                                  __nv_bfloat16* __restrict__ Hl) {
    __shared__ float red[16];
    int r = blockIdx.x;
    int bp = r / S_L, l = r - bp * S_L;
    int t = threadIdx.x;
    float v[3];
    #pragma unroll
    for (int j = 0; j < 3; j++) {
        int c = t + j * 256;
        float pre = P[bp * S_DIM + c] + PosP[l * S_DIM + c] + b1[c];
        v[j] = gelu_exact(pre);
    }
    ln_write(v[0], v[1], v[2], r, g1, be1, Hh, Hl, red);
}

__global__ void act2_kernel(const float* __restrict__ X,
                            const float* __restrict__ g2,
                            const float* __restrict__ be2,
                            __nv_bfloat16* __restrict__ Hh,
                            __nv_bfloat16* __restrict__ Hl) {
    __shared__ float red[16];
    int r = blockIdx.x;
    int t = threadIdx.x;
    size_t rb = (size_t)r * S_DIM;
    float v[3];
    #pragma unroll
    for (int j = 0; j < 3; j++) {
        int c = t + j * 256;
        v[j] = gelu_exact(X[rb + c]);
    }
    ln_write(v[0], v[1], v[2], r, g2, be2, Hh, Hl, red);
}

// ---------------- launch ----------------
extern "C" void kernel_launch(void* const* d_in, const int* in_sizes, int n_in,
                              void* d_out, int out_size) {
    (void)in_sizes; (void)n_in; (void)out_size;
    const float* hidden  = (const float*)d_in[0];
    const int*   pairs   = (const int*)d_in[1];
    const float* pos_emb = (const float*)d_in[2];
    const float* W1      = (const float*)d_in[3];
    const float* b1      = (const float*)d_in[4];
    const float* g1      = (const float*)d_in[5];
    const float* be1     = (const float*)d_in[6];
    const float* W2      = (const float*)d_in[7];
    const float* b2      = (const float*)d_in[8];
    const float* g2      = (const float*)d_in[9];
    const float* be2     = (const float*)d_in[10];
    const float* Wp      = (const float*)d_in[11];
    const float* bpv     = (const float*)d_in[12];
    const float* Wdec    = (const float*)d_in[13];
    float* out = (float*)d_out;

    void* sp = nullptr;
    cudaGetSymbolAddress(&sp, g_scratch);
    char* S = (char*)sp;
    __nv_bfloat16* A1h  = (__nv_bfloat16*)(S + OFF_A1H);
    __nv_bfloat16* A1l  = (__nv_bfloat16*)(S + OFF_A1L);
    __nv_bfloat16* W1th = (__nv_bfloat16*)(S + OFF_W1TH);
    __nv_bfloat16* W1tl = (__nv_bfloat16*)(S + OFF_W1TL);
    __nv_bfloat16* W2th = (__nv_bfloat16*)(S + OFF_W2TH);
    __nv_bfloat16* W2tl = (__nv_bfloat16*)(S + OFF_W2TL);
    __nv_bfloat16* Wpth = (__nv_bfloat16*)(S + OFF_WPTH);
    __nv_bfloat16* Wptl = (__nv_bfloat16*)(S + OFF_WPTL);
    __nv_bfloat16* Wdh  = (__nv_bfloat16*)(S + OFF_WDH);
    __nv_bfloat16* Wdl  = (__nv_bfloat16*)(S + OFF_WDL);
    float* P    = (float*)(S + OFF_P);
    float* PosP = (float*)(S + OFF_POSP);
    __nv_bfloat16* h1h = (__nv_bfloat16*)(S + OFF_H1H);
    __nv_bfloat16* h1l = (__nv_bfloat16*)(S + OFF_H1L);
    float* pre2 = (float*)(S + OFF_PRE2);
    __nv_bfloat16* h2h = (__nv_bfloat16*)(S + OFF_H2H);
    __nv_bfloat16* h2l = (__nv_bfloat16*)(S + OFF_H2L);
    __nv_bfloat16* h3h = (__nv_bfloat16*)(S + OFF_H3H);
    __nv_bfloat16* h3l = (__nv_bfloat16*)(S + OFF_H3L);

    constexpr int SM1 = 2 * (2 * 32 * 128 + 32768);   // MI=1: 81920
    constexpr int SM2 = 2 * (2 * 64 * 128 + 32768);   // MI=2: 98304
    cudaFuncSetAttribute(gemm_kl<1>,
                         cudaFuncAttributeMaxDynamicSharedMemorySize, SM1);
    cudaFuncSetAttribute(gemm_kl<2>,
                         cudaFuncAttributeMaxDynamicSharedMemorySize, SM2);
    cudaFuncSetAttribute(gemm_nl,
                         cudaFuncAttributeMaxDynamicSharedMemorySize, NL_SMEM);

    // 1: all prep (gather + weight transposes/splits + posmat)
    prep_all_kernel<<<PB_POS, 256>>>(hidden, pairs, pos_emb, W1, W2, Wp, Wdec,
                                     A1h, A1l, W1th, W1tl, W2th, W2tl,
                                     Wpth, Wptl, Wdh, Wdl, PosP);

    // 2: GEMM1  P[256,768] = Acat[256,1536] @ W1t^T   (48 CTAs)
    gemm_kl<1><<<dim3(S_BP / 32, S_DIM / 128), 256, SM1>>>(
        S_BP, S_DIM, S_DIN2, A1h, A1l, W1th, W1tl,
        nullptr, P, nullptr, nullptr);

    // 3: expand over L + gelu + LN1 -> h1
    expand_act_kernel<<<S_ROWS, 256>>>(P, PosP, b1, g1, be1, h1h, h1l);

    // 4: GEMM2  pre2[5120,768] = h1 @ W2t^T + b2   <-- ncu capture target
    gemm_kl<2><<<dim3(S_ROWS / 64, S_DIM / 128), 256, SM2>>>(
        S_ROWS, S_DIM, S_DIM, h1h, h1l, W2th, W2tl,
        b2, pre2, nullptr, nullptr);

    // 5: gelu + LN2 -> h2
    act2_kernel<<<S_ROWS, 256>>>(pre2, g2, be2, h2h, h2l);

    // 6: GEMM3  h3[5120,128] = h2 @ Wpt^T + bp
    gemm_kl<2><<<dim3(S_ROWS / 64, 1), 256, SM2>>>(
        S_ROWS, S_EMB, S_DIM, h2h, h2l, Wpth, Wptl,
        bpv, nullptr, h3h, h3l);

    // 7: GEMM4  out[5120,30522] = h3 @ Wdec^T  (persistent, A-resident)
    gemm_nl<<<148, 256, NL_SMEM>>>(
        S_ROWS, S_VOCAB, h3h, h3l, Wdh, Wdl, out);
}

// round 6
// speedup vs baseline: 1.0858x; 1.0858x over previous
#include <cuda_runtime.h>
#include <cuda_bf16.h>
#include <cstdint>
#include <cstddef>

constexpr int S_BS = 8, S_SEQ = 512, S_DIM = 768, S_NP = 32, S_PE = 200;
constexpr int S_L = 20, S_EMB = 128, S_VOCAB = 30522;
constexpr int S_BP = S_BS * S_NP;            // 256
constexpr int S_ROWS = S_BP * S_L;           // 5120
constexpr int S_DIN2 = 2 * S_DIM;            // 1536

// ---------------- scratch ----------------
constexpr size_t SZ_A1   = (size_t)S_BP * S_DIN2 * 2;      // bf16
constexpr size_t SZ_W1T  = (size_t)S_DIM * S_DIN2 * 2;
constexpr size_t SZ_W2T  = (size_t)S_DIM * S_DIM * 2;
constexpr size_t SZ_WPT  = (size_t)S_EMB * S_DIM * 2;
constexpr size_t SZ_WD   = (size_t)S_VOCAB * S_EMB * 2;
constexpr size_t SZ_P    = (size_t)S_BP * S_DIM * 4;       // f32
constexpr size_t SZ_POSP = (size_t)S_L * S_DIM * 4;
constexpr size_t SZ_H1   = (size_t)S_ROWS * S_DIM * 2;
constexpr size_t SZ_PRE2 = (size_t)S_ROWS * S_DIM * 4;
constexpr size_t SZ_H3   = (size_t)S_ROWS * S_EMB * 2;

constexpr size_t OFF_A1H  = 0;
constexpr size_t OFF_A1L  = OFF_A1H  + SZ_A1;
constexpr size_t OFF_W1TH = OFF_A1L  + SZ_A1;
constexpr size_t OFF_W1TL = OFF_W1TH + SZ_W1T;
constexpr size_t OFF_W2TH = OFF_W1TL + SZ_W1T;
constexpr size_t OFF_W2TL = OFF_W2TH + SZ_W2T;
constexpr size_t OFF_WPTH = OFF_W2TL + SZ_W2T;
constexpr size_t OFF_WPTL = OFF_WPTH + SZ_WPT;
constexpr size_t OFF_WDH  = OFF_WPTL + SZ_WPT;
constexpr size_t OFF_WDL  = OFF_WDH  + SZ_WD;
constexpr size_t OFF_P    = OFF_WDL  + SZ_WD;
constexpr size_t OFF_POSP = OFF_P    + SZ_P;
constexpr size_t OFF_H1H  = OFF_POSP + SZ_POSP;
constexpr size_t OFF_H1L  = OFF_H1H  + SZ_H1;
constexpr size_t OFF_PRE2 = OFF_H1L  + SZ_H1;
constexpr size_t OFF_H2H  = OFF_PRE2 + SZ_PRE2;
constexpr size_t OFF_H2L  = OFF_H2H  + SZ_H1;
constexpr size_t OFF_H3H  = OFF_H2L  + SZ_H1;
constexpr size_t OFF_H3L  = OFF_H3H  + SZ_H3;
constexpr size_t SCRATCH_BYTES = OFF_H3L + SZ_H3;

__device__ __align__(1024) unsigned char g_scratch[SCRATCH_BYTES];

// ---------------- helpers ----------------
__device__ __forceinline__ void split2(float v, __nv_bfloat16& hi, __nv_bfloat16& lo) {
    __nv_bfloat16 h = __float2bfloat16(v);
    hi = h;
    lo = __float2bfloat16(v - __bfloat162float(h));
}

__device__ __forceinline__ float gelu_exact(float x) {
    return 0.5f * x * (1.0f + erff(x * 0.70710678118654752440f));
}

__device__ __forceinline__ uint32_t sm_u32(const void* p) {
    uint32_t a;
    asm("{ .reg .u64 t; cvta.to.shared.u64 t, %1; cvt.u32.u64 %0, t; }"
        : "=r"(a) : "l"(p));
    return a;
}

#define MMA_BF16(c, a, b)                                                     \
    asm volatile(                                                             \
        "mma.sync.aligned.m16n8k16.row.col.f32.bf16.bf16.f32 "                \
        "{%0,%1,%2,%3},{%4,%5,%6,%7},{%8,%9},{%0,%1,%2,%3};\n"                \
        : "+f"((c)[0]), "+f"((c)[1]), "+f"((c)[2]), "+f"((c)[3])              \
        : "r"((a)[0]), "r"((a)[1]), "r"((a)[2]), "r"((a)[3]),                 \
          "r"((b)[0]), "r"((b)[1]))

#define LDSM4(r, a)                                                           \
    asm volatile("ldmatrix.sync.aligned.m8n8.x4.shared.b16 "                  \
                 "{%0,%1,%2,%3}, [%4];"                                       \
                 : "=r"((r)[0]), "=r"((r)[1]), "=r"((r)[2]), "=r"((r)[3])     \
                 : "r"(a))

#define CP16(dst, src, sz)                                                    \
    asm volatile("cp.async.cg.shared.global [%0], [%1], 16, %2;\n"            \
                 :: "r"(dst), "l"(src), "r"(sz))

#define CP_COMMIT()  asm volatile("cp.async.commit_group;\n" ::: "memory")
#define CP_WAIT(n)   asm volatile("cp.async.wait_group %0;\n" :: "n"(n) : "memory")

__device__ __forceinline__ uint32_t swz(uint32_t off) {
    return off ^ ((off >> 3) & 0x70);
}

// ---------------- fused prep kernel ----------------
__device__ void do_transpose32(const float* __restrict__ W, int K, int N,
                               __nv_bfloat16* __restrict__ Th,
                               __nv_bfloat16* __restrict__ Tl,
                               int tilex, int tiley) {
    __shared__ float tile[32][33];
    int t = threadIdx.x;
    int x = t & 31, y = t >> 5;
    int k0 = tiley * 32, n0 = tilex * 32;
    #pragma unroll
    for (int i = 0; i < 4; i++) {
        int kk = y + i * 8;
        tile[kk][x] = W[(size_t)(k0 + kk) * N + n0 + x];
    }
    __syncthreads();
    #pragma unroll
    for (int i = 0; i < 4; i++) {
        int nn = y + i * 8;
        float v = tile[x][nn];
        size_t o = (size_t)(n0 + nn) * K + k0 + x;
        split2(v, Th[o], Tl[o]);
    }
}

constexpr int PB_GA = (S_BP * S_DIN2) / 256;                 // 1536
constexpr int PB_W1 = PB_GA + (S_DIM / 32) * (S_DIN2 / 32);  // 2688
constexpr int PB_W2 = PB_W1 + (S_DIM / 32) * (S_DIM / 32);   // 3264
constexpr int PB_WP = PB_W2 + (S_EMB / 32) * (S_DIM / 32);   // 3360
constexpr int WD_ELEMS = S_VOCAB * S_EMB;                     // 3906816
constexpr int PB_WD = PB_WP + (WD_ELEMS + 1023) / 1024;       // 7176
constexpr int PB_POS = PB_WD + S_L;                           // 7196

__global__ void prep_all_kernel(const float* __restrict__ hidden,
                                const int* __restrict__ pairs,
                                const float* __restrict__ pos_emb,
                                const float* __restrict__ W1,
                                const float* __restrict__ W2,
                                const float* __restrict__ Wp,
                                const float* __restrict__ Wdec,
                                __nv_bfloat16* __restrict__ A1h, __nv_bfloat16* __restrict__ A1l,
                                __nv_bfloat16* __restrict__ W1th, __nv_bfloat16* __restrict__ W1tl,
                                __nv_bfloat16* __restrict__ W2th, __nv_bfloat16* __restrict__ W2tl,
                                __nv_bfloat16* __restrict__ Wpth, __nv_bfloat16* __restrict__ Wptl,
                                __nv_bfloat16* __restrict__ Wdh,  __nv_bfloat16* __restrict__ Wdl,
                                float* __restrict__ PosP) {
    int bx = blockIdx.x;
    int tid = threadIdx.x;
    if (bx < PB_GA) {
        int id = bx * 256 + tid;
        int bp = id / S_DIN2;
        int k  = id - bp * S_DIN2;
        int side = (k >= S_DIM) ? 1 : 0;
        int col  = k - side * S_DIM;
        int s = pairs[bp * 2 + side];
        int b = bp >> 5;
        float v = hidden[((size_t)(b * S_SEQ + s)) * S_DIM + col];
        split2(v, A1h[id], A1l[id]);
    } else if (bx < PB_W1) {
        int b = bx - PB_GA;
        do_transpose32(W1, S_DIN2, S_DIM, W1th, W1tl,
                       b % (S_DIM / 32), b / (S_DIM / 32));
    } else if (bx < PB_W2) {
        int b = bx - PB_W1;
        do_transpose32(W2, S_DIM, S_DIM, W2th, W2tl,
                       b % (S_DIM / 32), b / (S_DIM / 32));
    } else if (bx < PB_WP) {
        int b = bx - PB_W2;
        do_transpose32(Wp, S_DIM, S_EMB, Wpth, Wptl,
                       b % (S_EMB / 32), b / (S_EMB / 32));
    } else if (bx < PB_WD) {
        int base = (bx - PB_WP) * 1024;
        #pragma unroll
        for (int u = 0; u < 4; u++) {
            int id = base + tid + u * 256;
            if (id < WD_ELEMS) split2(Wdec[id], Wdh[id], Wdl[id]);
        }
    } else {
        int l = bx - PB_WD;
        __shared__ float sp[S_PE];
        if (tid < S_PE) sp[tid] = pos_emb[l * S_PE + tid];
        __syncthreads();
        #pragma unroll
        for (int j = 0; j < 3; j++) {
            int n = tid + j * 256;
            float a = 0.f;
            #pragma unroll 4
            for (int k = 0; k < S_PE; k++)
                a += sp[k] * W1[(size_t)(S_DIN2 + k) * S_DIM + n];
            PosP[l * S_DIM + n] = a;
        }
    }
}

// ---------------- ldmatrix + mma compute for one 64-k chunk ----------------
// smem matrices: [row][128B] rows with SW128 swizzle.
// Interleaved per-acc 3-term ordering (R4 empirically best).
template<int MI>
__device__ __forceinline__ void chunk_mma(uint32_t sAh, uint32_t sAl,
                                          uint32_t sBh, uint32_t sBl,
                                          int m0, int n0, int lane,
                                          float acc[][4][4]) {
    #pragma unroll
    for (int ks = 0; ks < 4; ks++) {
        uint32_t ah[MI][4], al[MI][4], bh[8], bl[8];
        #pragma unroll
        for (int mi = 0; mi < MI; mi++) {
            int row = m0 + mi * 16 + (lane & 15);
            int c16 = ks * 2 + (lane >> 4);
            uint32_t off = swz((uint32_t)(row * 128 + c16 * 16));
            LDSM4(ah[mi], sAh + off);
            LDSM4(al[mi], sAl + off);
        }
        #pragma unroll
        for (int np = 0; np < 2; np++) {
            int row = n0 + np * 16 + ((lane >> 4) << 3) + (lane & 7);
            int c16 = ks * 2 + ((lane >> 3) & 1);
            uint32_t off = swz((uint32_t)(row * 128 + c16 * 16));
            LDSM4(&bh[np * 4], sBh + off);
            LDSM4(&bl[np * 4], sBl + off);
        }
        #pragma unroll
        for (int mi = 0; mi < MI; mi++)
            #pragma unroll
            for (int nj = 0; nj < 4; nj++) {
                MMA_BF16(acc[mi][nj], ah[mi], &bh[nj * 2]);
                MMA_BF16(acc[mi][nj], ah[mi], &bl[nj * 2]);
                MMA_BF16(acc[mi][nj], al[mi], &bh[nj * 2]);
            }
    }
}

// ---------------- k-loop GEMM: C[M,N] = A[M,K] @ Bt[N,K]^T (+bias) ----------
template<int MI>
__global__ void __launch_bounds__(256)
gemm_kl(int M, int N, int K,
        const __nv_bfloat16* __restrict__ Ahp, const __nv_bfloat16* __restrict__ Alp,
        const __nv_bfloat16* __restrict__ Bhp, const __nv_bfloat16* __restrict__ Blp,
        const float* __restrict__ bias,
        float* __restrict__ Cf,
        __nv_bfloat16* __restrict__ Ch, __nv_bfloat16* __restrict__ Cl) {
    constexpr int MT = MI * 32;
    constexpr int AB = MT * 128;            // bytes per A matrix per stage
    constexpr int SS = 2 * AB + 32768;      // stage bytes
    extern __shared__ __align__(1024) unsigned char smraw[];
    const uint32_t smb = sm_u32(smraw);
    const int tid = threadIdx.x, lane = tid & 31, warp = tid >> 5;
    const int m0 = (warp >> 2) * MI * 16, n0 = (warp & 3) * 32;
    const int am0 = blockIdx.x * MT, bn0 = blockIdx.y * 128;
    const long rowB = (long)K * 2;
    const int nch = K >> 6;

    float acc[MI][4][4];
    #pragma unroll
    for (int a = 0; a < MI; a++)
        #pragma unroll
        for (int b = 0; b < 4; b++)
            #pragma unroll
            for (int c = 0; c < 4; c++) acc[a][b][c] = 0.f;

    auto load_stage = [&](int c, int s) {
        const uint32_t sb = smb + (uint32_t)s * SS;
        constexpr int AU = AB / 16;
        #pragma unroll
        for (int i = 0; i < (2 * AU) / 256; i++) {
            int u = tid + i * 256;
            int hi = (u >= AU); int v = u - hi * AU;
            int row = v >> 3, j = v & 7;
            uint32_t off = swz((uint32_t)(row * 128 + j * 16));
            const char* src = (hi ? (const char*)Alp : (const char*)Ahp)
                              + (long)(am0 + row) * rowB + (long)c * 128 + j * 16;
            CP16(sb + (uint32_t)hi * AB + off, src, 16);
        }
        #pragma unroll
        for (int i = 0; i < 8; i++) {
            int u = tid + i * 256;
            int hi = (u >= 1024); int v = u - hi * 1024;
            int row = v >> 3, j = v & 7;
            int grow = bn0 + row;
            int ok = (grow < N) ? 16 : 0;
            uint32_t off = swz((uint32_t)(row * 128 + j * 16));
            const char* src = (hi ? (const char*)Blp : (const char*)Bhp)
                              + (long)(ok ? grow : 0) * rowB + (long)c * 128 + j * 16;
            CP16(sb + 2u * AB + (uint32_t)hi * 16384u + off, src, ok);
        }
        CP_COMMIT();
    };

    load_stage(0, 0);
    for (int c = 0; c < nch; c++) {
        int s = c & 1;
        if (c + 1 < nch) { load_stage(c + 1, s ^ 1); CP_WAIT(1); }
        else             { CP_WAIT(0); }
        __syncthreads();
        uint32_t sb = smb + (uint32_t)s * SS;
        chunk_mma<MI>(sb, sb + AB, sb + 2 * AB, sb + 2 * AB + 16384,
                      m0, n0, lane, acc);
        __syncthreads();
    }

    const int g = lane >> 2, tg = lane & 3;
    #pragma unroll
    for (int mi = 0; mi < MI; mi++) {
        int r0 = am0 + m0 + mi * 16 + g;
        size_t base0 = (size_t)r0 * N;
        size_t base1 = (size_t)(r0 + 8) * N;
        #pragma unroll
        for (int nj = 0; nj < 4; nj++) {
            int c0 = bn0 + n0 + nj * 8 + tg * 2;
            float v0 = acc[mi][nj][0], v1 = acc[mi][nj][1];
            float v2 = acc[mi][nj][2], v3 = acc[mi][nj][3];
            if (bias) {
                float bb0 = bias[c0], bb1 = bias[c0 + 1];
                v0 += bb0; v1 += bb1; v2 += bb0; v3 += bb1;
            }
            if (Cf) {
                *(float2*)(Cf + base0 + c0) = make_float2(v0, v1);
                *(float2*)(Cf + base1 + c0) = make_float2(v2, v3);
            } else {
                split2(v0, Ch[base0 + c0],     Cl[base0 + c0]);
                split2(v1, Ch[base0 + c0 + 1], Cl[base0 + c0 + 1]);
                split2(v2, Ch[base1 + c0],     Cl[base1 + c0]);
                split2(v3, Ch[base1 + c0 + 1], Cl[base1 + c0 + 1]);
            }
        }
    }
}

// ---------------- persistent n-loop GEMM for GEMM4 (K=128 fixed) -----------
// 512 threads / 16 warps (4 per SMSP) for latency hiding; warp tile 32x32.
// smem: A [chunk(2)][hi/lo][128x128B] = 64KB; B stages at 64KB + s*64KB.
constexpr int NL_SMEM = 196608;

__global__ void __launch_bounds__(512)
gemm_nl(int M, int N,
        const __nv_bfloat16* __restrict__ Ahp, const __nv_bfloat16* __restrict__ Alp,
        const __nv_bfloat16* __restrict__ Bhp, const __nv_bfloat16* __restrict__ Blp,
        float* __restrict__ Cf) {
    extern __shared__ __align__(1024) unsigned char smraw[];
    const uint32_t smb = sm_u32(smraw);
    const int tid = threadIdx.x, lane = tid & 31, warp = tid >> 5;
    const int m0 = (warp >> 2) * 32, n0 = (warp & 3) * 32;
    const int ntiles = (N + 127) >> 7;
    const int W = (M >> 7) * ntiles;
    const int Q = W / gridDim.x, R = W % gridDim.x;
    const int k = blockIdx.x;
    const int beg = k * Q + min(k, R);
    const int cnt = Q + (k < R ? 1 : 0);
    if (cnt == 0) return;

    auto load_A = [&](int m) {
        #pragma unroll
        for (int i = 0; i < 8; i++) {
            int u = tid + i * 512;            // [0,4096)
            int c = u >> 11; int v = u & 2047;
            int hi = v >> 10; int v2 = v & 1023;
            int row = v2 >> 3, j = v2 & 7;
            uint32_t off = swz((uint32_t)(row * 128 + j * 16));
            const char* src = (hi ? (const char*)Alp : (const char*)Ahp)
                              + (long)(m * 128 + row) * 256 + c * 128 + j * 16;
            CP16(smb + (uint32_t)c * 32768u + (uint32_t)hi * 16384u + off, src, 16);
        }
        CP_COMMIT();
    };
    auto load_B = [&](int n, int s) {
        #pragma unroll
        for (int i = 0; i < 8; i++) {
            int u = tid + i * 512;
            int c = u >> 11; int v = u & 2047;
            int hi = v >> 10; int v2 = v & 1023;
            int row = v2 >> 3, j = v2 & 7;
            int grow = n * 128 + row;
            int ok = (grow < N) ? 16 : 0;
            uint32_t off = swz((uint32_t)(row * 128 + j * 16));
            const char* src = (hi ? (const char*)Blp : (const char*)Bhp)
                              + (long)(ok ? grow : 0) * 256 + c * 128 + j * 16;
            CP16(smb + 65536u + (uint32_t)s * 65536u
                 + (uint32_t)c * 32768u + (uint32_t)hi * 16384u + off, src, ok);
        }
        CP_COMMIT();
    };

    int loadedm = beg / ntiles;
    load_A(loadedm);
    load_B(beg % ntiles, 0);

    const int g = lane >> 2, tg = lane & 3;
    for (int it = 0; it < cnt; it++) {
        int w = beg + it, s = it & 1;
        int mm = w / ntiles, nn = w % ntiles;
        if (mm != loadedm) { load_A(mm); loadedm = mm; }
        if (it + 1 < cnt) {
            int wn = w + 1;
            load_B(wn % ntiles, s ^ 1);
            CP_WAIT(1);
        } else {
            CP_WAIT(0);
        }
        __syncthreads();

        float acc[2][4][4];
        #pragma unroll
        for (int a = 0; a < 2; a++)
            #pragma unroll
            for (int b = 0; b < 4; b++)
                #pragma unroll
                for (int c = 0; c < 4; c++) acc[a][b][c] = 0.f;

        uint32_t bB = smb + 65536u + (uint32_t)s * 65536u;
        #pragma unroll
        for (int c = 0; c < 2; c++) {
            uint32_t aoff = smb + (uint32_t)c * 32768u;
            uint32_t boff = bB + (uint32_t)c * 32768u;
            chunk_mma<2>(aoff, aoff + 16384u, boff, boff + 16384u,
                         m0, n0, lane, acc);
        }

        #pragma unroll
        for (int mi = 0; mi < 2; mi++) {
            int r0 = mm * 128 + m0 + mi * 16 + g;
            size_t base0 = (size_t)r0 * N;
            size_t base1 = (size_t)(r0 + 8) * N;
            #pragma unroll
            for (int nj = 0; nj < 4; nj++) {
                int c0 = nn * 128 + n0 + nj * 8 + tg * 2;
                if (c0 + 1 < N) {
                    *(float2*)(Cf + base0 + c0) =
                        make_float2(acc[mi][nj][0], acc[mi][nj][1]);
                    *(float2*)(Cf + base1 + c0) =
                        make_float2(acc[mi][nj][2], acc[mi][nj][3]);
                } else if (c0 < N) {
                    Cf[base0 + c0] = acc[mi][nj][0];
                    Cf[base1 + c0] = acc[mi][nj][2];
                }
            }
        }
        __syncthreads();
    }
}

// ---------------- gelu + LN (one 768-row per 256-thread block) ----------------
__device__ __forceinline__ void ln_write(float v0, float v1, float v2, int r,
                                         const float* __restrict__ gam,
                                         const float* __restrict__ bet,
                                         __nv_bfloat16* __restrict__ Hh,
                                         __nv_bfloat16* __restrict__ Hl,
                                         float* red) {
    int t = threadIdx.x;
    float s1 = v0 + v1 + v2;
    float s2 = v0 * v0 + v1 * v1 + v2 * v2;
    #pragma unroll
    for (int o = 16; o; o >>= 1) {
        s1 += __shfl_xor_sync(0xffffffffu, s1, o);
        s2 += __shfl_xor_sync(0xffffffffu, s2, o);
    }
    if ((t & 31) == 0) { red[t >> 5] = s1; red[8 + (t >> 5)] = s2; }
    __syncthreads();
    s1 = 0.f; s2 = 0.f;
    #pragma unroll
    for (int i = 0; i < 8; i++) { s1 += red[i]; s2 += red[8 + i]; }
    float mean = s1 * (1.0f / S_DIM);
    float var  = s2 * (1.0f / S_DIM) - mean * mean;
    float rstd = rsqrtf(fmaxf(var, 0.0f) + 1e-12f);
    size_t rb = (size_t)r * S_DIM;
    float v[3] = {v0, v1, v2};
    #pragma unroll
    for (int j = 0; j < 3; j++) {
        int c = t + j * 256;
        float y = (v[j] - mean) * rstd * gam[c] + bet[c];
        split2(y, Hh[rb + c], Hl[rb + c]);
    }
}

__global__ void expand_act_kernel(const float* __restrict__ P,
                                  const float* __restrict__ PosP,
                                  const float* __restrict__ b1,
                                  const float* __restrict__ g1,
                                  const float* __restrict__ be1,
                                  __nv_bfloat16* __restrict__ Hh,
                                  __nv_bfloat16* __restrict__ Hl) {
    __shared__ float red[16];
    int r = blockIdx.x;
    int bp = r / S_L, l = r - bp * S_L;
    int t = threadIdx.x;
    float v[3];
    #pragma unroll
    for (int j = 0; j < 3; j++) {
        int c = t + j * 256;
        float pre = P[bp * S_DIM + c] + PosP[l * S_DIM + c] + b1[c];
        v[j] = gelu_exact(pre);
    }
    ln_write(v[0], v[1], v[2], r, g1, be1, Hh, Hl, red);
}

__global__ void act2_kernel(const float* __restrict__ X,
                            const float* __restrict__ g2,
                            const float* __restrict__ be2,
                            __nv_bfloat16* __restrict__ Hh,
                            __nv_bfloat16* __restrict__ Hl) {
    __shared__ float red[16];
    int r = blockIdx.x;
    int t = threadIdx.x;
    size_t rb = (size_t)r * S_DIM;
    float v[3];
    #pragma unroll
    for (int j = 0; j < 3; j++) {
        int c = t + j * 256;
        v[j] = gelu_exact(X[rb + c]);
    }
    ln_write(v[0], v[1], v[2], r, g2, be2, Hh, Hl, red);
}

// ---------------- launch ----------------
extern "C" void kernel_launch(void* const* d_in, const int* in_sizes, int n_in,
                              void* d_out, int out_size) {
    (void)in_sizes; (void)n_in; (void)out_size;
    const float* hidden  = (const float*)d_in[0];
    const int*   pairs   = (const int*)d_in[1];
    const float* pos_emb = (const float*)d_in[2];
    const float* W1      = (const float*)d_in[3];
    const float* b1      = (const float*)d_in[4];
    const float* g1      = (const float*)d_in[5];
    const float* be1     = (const float*)d_in[6];
    const float* W2      = (const float*)d_in[7];
    const float* b2      = (const float*)d_in[8];
    const float* g2      = (const float*)d_in[9];
    const float* be2     = (const float*)d_in[10];
    const float* Wp      = (const float*)d_in[11];
    const float* bpv     = (const float*)d_in[12];
    const float* Wdec    = (const float*)d_in[13];
    float* out = (float*)d_out;

    void* sp = nullptr;
    cudaGetSymbolAddress(&sp, g_scratch);
    char* S = (char*)sp;
    __nv_bfloat16* A1h  = (__nv_bfloat16*)(S + OFF_A1H);
    __nv_bfloat16* A1l  = (__nv_bfloat16*)(S + OFF_A1L);
    __nv_bfloat16* W1th = (__nv_bfloat16*)(S + OFF_W1TH);
    __nv_bfloat16* W1tl = (__nv_bfloat16*)(S + OFF_W1TL);
    __nv_bfloat16* W2th = (__nv_bfloat16*)(S + OFF_W2TH);
    __nv_bfloat16* W2tl = (__nv_bfloat16*)(S + OFF_W2TL);
    __nv_bfloat16* Wpth = (__nv_bfloat16*)(S + OFF_WPTH);
    __nv_bfloat16* Wptl = (__nv_bfloat16*)(S + OFF_WPTL);
    __nv_bfloat16* Wdh  = (__nv_bfloat16*)(S + OFF_WDH);
    __nv_bfloat16* Wdl  = (__nv_bfloat16*)(S + OFF_WDL);
    float* P    = (float*)(S + OFF_P);
    float* PosP = (float*)(S + OFF_POSP);
    __nv_bfloat16* h1h = (__nv_bfloat16*)(S + OFF_H1H);
    __nv_bfloat16* h1l = (__nv_bfloat16*)(S + OFF_H1L);
    float* pre2 = (float*)(S + OFF_PRE2);
    __nv_bfloat16* h2h = (__nv_bfloat16*)(S + OFF_H2H);
    __nv_bfloat16* h2l = (__nv_bfloat16*)(S + OFF_H2L);
    __nv_bfloat16* h3h = (__nv_bfloat16*)(S + OFF_H3H);
    __nv_bfloat16* h3l = (__nv_bfloat16*)(S + OFF_H3L);

    constexpr int SM1 = 2 * (2 * 32 * 128 + 32768);   // MI=1: 81920
    constexpr int SM2 = 2 * (2 * 64 * 128 + 32768);   // MI=2: 98304
    cudaFuncSetAttribute(gemm_kl<1>,
                         cudaFuncAttributeMaxDynamicSharedMemorySize, SM1);
    cudaFuncSetAttribute(gemm_kl<2>,
                         cudaFuncAttributeMaxDynamicSharedMemorySize, SM2);
    cudaFuncSetAttribute(gemm_nl,
                         cudaFuncAttributeMaxDynamicSharedMemorySize, NL_SMEM);

    // 1: all prep (gather + weight transposes/splits + posmat)
    prep_all_kernel<<<PB_POS, 256>>>(hidden, pairs, pos_emb, W1, W2, Wp, Wdec,
                                     A1h, A1l, W1th, W1tl, W2th, W2tl,
                                     Wpth, Wptl, Wdh, Wdl, PosP);

    // 2: GEMM1  P[256,768] = Acat[256,1536] @ W1t^T   (48 CTAs)
    gemm_kl<1><<<dim3(S_BP / 32, S_DIM / 128), 256, SM1>>>(
        S_BP, S_DIM, S_DIN2, A1h, A1l, W1th, W1tl,
        nullptr, P, nullptr, nullptr);

    // 3: expand over L + gelu + LN1 -> h1
    expand_act_kernel<<<S_ROWS, 256>>>(P, PosP, b1, g1, be1, h1h, h1l);

    // 4: GEMM2  pre2[5120,768] = h1 @ W2t^T + b2   <-- ncu capture target
    gemm_kl<2><<<dim3(S_ROWS / 64, S_DIM / 128), 256, SM2>>>(
        S_ROWS, S_DIM, S_DIM, h1h, h1l, W2th, W2tl,
        b2, pre2, nullptr, nullptr);

    // 5: gelu + LN2 -> h2
    act2_kernel<<<S_ROWS, 256>>>(pre2, g2, be2, h2h, h2l);

    // 6: GEMM3  h3[5120,128] = h2 @ Wpt^T + bp
    gemm_kl<2><<<dim3(S_ROWS / 64, 1), 256, SM2>>>(
        S_ROWS, S_EMB, S_DIM, h2h, h2l, Wpth, Wptl,
        bpv, nullptr, h3h, h3l);

    // 7: GEMM4  out[5120,30522] = h3 @ Wdec^T  (persistent, 16 warps)
    gemm_nl<<<148, 512, NL_SMEM>>>(
        S_ROWS, S_VOCAB, h3h, h3l, Wdh, Wdl, out);
}

// round 7
// speedup vs baseline: 1.1500x; 1.0591x over previous
#include <cuda_runtime.h>
#include <cuda_bf16.h>
#include <cuda_fp16.h>
#include <cstdint>
#include <cstddef>

constexpr int S_BS = 8, S_SEQ = 512, S_DIM = 768, S_NP = 32, S_PE = 200;
constexpr int S_L = 20, S_EMB = 128, S_VOCAB = 30522;
constexpr int S_BP = S_BS * S_NP;            // 256
constexpr int S_ROWS = S_BP * S_L;           // 5120
constexpr int S_DIN2 = 2 * S_DIM;            // 1536

// ---------------- scratch ----------------
constexpr size_t SZ_A1   = (size_t)S_BP * S_DIN2 * 2;      // bf16
constexpr size_t SZ_W1T  = (size_t)S_DIM * S_DIN2 * 2;
constexpr size_t SZ_W2T  = (size_t)S_DIM * S_DIM * 2;
constexpr size_t SZ_WPT  = (size_t)S_EMB * S_DIM * 2;
constexpr size_t SZ_WD   = (size_t)S_VOCAB * S_EMB * 2;    // fp16 each (hi & lo)
constexpr size_t SZ_P    = (size_t)S_BP * S_DIM * 4;       // f32
constexpr size_t SZ_POSP = (size_t)S_L * S_DIM * 4;
constexpr size_t SZ_H1   = (size_t)S_ROWS * S_DIM * 2;
constexpr size_t SZ_PRE2 = (size_t)S_ROWS * S_DIM * 4;
constexpr size_t SZ_H3   = (size_t)S_ROWS * S_EMB * 2;     // single fp16

constexpr size_t OFF_A1H  = 0;
constexpr size_t OFF_A1L  = OFF_A1H  + SZ_A1;
constexpr size_t OFF_W1TH = OFF_A1L  + SZ_A1;
constexpr size_t OFF_W1TL = OFF_W1TH + SZ_W1T;
constexpr size_t OFF_W2TH = OFF_W1TL + SZ_W1T;
constexpr size_t OFF_W2TL = OFF_W2TH + SZ_W2T;
constexpr size_t OFF_WPTH = OFF_W2TL + SZ_W2T;
constexpr size_t OFF_WPTL = OFF_WPTH + SZ_WPT;
constexpr size_t OFF_WDH  = OFF_WPTL + SZ_WPT;
constexpr size_t OFF_WDL  = OFF_WDH  + SZ_WD;
constexpr size_t OFF_P    = OFF_WDL  + SZ_WD;
constexpr size_t OFF_POSP = OFF_P    + SZ_P;
constexpr size_t OFF_H1H  = OFF_POSP + SZ_POSP;
constexpr size_t OFF_H1L  = OFF_H1H  + SZ_H1;
constexpr size_t OFF_PRE2 = OFF_H1L  + SZ_H1;
constexpr size_t OFF_H2H  = OFF_PRE2 + SZ_PRE2;
constexpr size_t OFF_H2L  = OFF_H2H  + SZ_H1;
constexpr size_t OFF_H3   = OFF_H2L  + SZ_H1;
constexpr size_t SCRATCH_BYTES = OFF_H3 + SZ_H3;

__device__ __align__(1024) unsigned char g_scratch[SCRATCH_BYTES];

// ---------------- helpers ----------------
__device__ __forceinline__ void split2(float v, __nv_bfloat16& hi, __nv_bfloat16& lo) {
    __nv_bfloat16 h = __float2bfloat16(v);
    hi = h;
    lo = __float2bfloat16(v - __bfloat162float(h));
}

__device__ __forceinline__ void split2h(float v, __half& hi, __half& lo) {
    __half h = __float2half(v);
    hi = h;
    lo = __float2half(v - __half2float(h));
}

__device__ __forceinline__ float gelu_exact(float x) {
    return 0.5f * x * (1.0f + erff(x * 0.70710678118654752440f));
}

__device__ __forceinline__ uint32_t sm_u32(const void* p) {
    uint32_t a;
    asm("{ .reg .u64 t; cvta.to.shared.u64 t, %1; cvt.u32.u64 %0, t; }"
        : "=r"(a) : "l"(p));
    return a;
}

#define MMA_BF16(c, a, b)                                                     \
    asm volatile(                                                             \
        "mma.sync.aligned.m16n8k16.row.col.f32.bf16.bf16.f32 "                \
        "{%0,%1,%2,%3},{%4,%5,%6,%7},{%8,%9},{%0,%1,%2,%3};\n"                \
        : "+f"((c)[0]), "+f"((c)[1]), "+f"((c)[2]), "+f"((c)[3])              \
        : "r"((a)[0]), "r"((a)[1]), "r"((a)[2]), "r"((a)[3]),                 \
          "r"((b)[0]), "r"((b)[1]))

#define MMA_F16(c, a, b)                                                      \
    asm volatile(                                                             \
        "mma.sync.aligned.m16n8k16.row.col.f32.f16.f16.f32 "                  \
        "{%0,%1,%2,%3},{%4,%5,%6,%7},{%8,%9},{%0,%1,%2,%3};\n"                \
        : "+f"((c)[0]), "+f"((c)[1]), "+f"((c)[2]), "+f"((c)[3])              \
        : "r"((a)[0]), "r"((a)[1]), "r"((a)[2]), "r"((a)[3]),                 \
          "r"((b)[0]), "r"((b)[1]))

#define LDSM4(r, a)                                                           \
    asm volatile("ldmatrix.sync.aligned.m8n8.x4.shared.b16 "                  \
                 "{%0,%1,%2,%3}, [%4];"                                       \
                 : "=r"((r)[0]), "=r"((r)[1]), "=r"((r)[2]), "=r"((r)[3])     \
                 : "r"(a))

#define CP16(dst, src, sz)                                                    \
    asm volatile("cp.async.cg.shared.global [%0], [%1], 16, %2;\n"            \
                 :: "r"(dst), "l"(src), "r"(sz))

#define CP_COMMIT()  asm volatile("cp.async.commit_group;\n" ::: "memory")
#define CP_WAIT(n)   asm volatile("cp.async.wait_group %0;\n" :: "n"(n) : "memory")

__device__ __forceinline__ uint32_t swz(uint32_t off) {
    return off ^ ((off >> 3) & 0x70);
}

// ---------------- fused prep kernel ----------------
__device__ void do_transpose32(const float* __restrict__ W, int K, int N,
                               __nv_bfloat16* __restrict__ Th,
                               __nv_bfloat16* __restrict__ Tl,
                               int tilex, int tiley) {
    __shared__ float tile[32][33];
    int t = threadIdx.x;
    int x = t & 31, y = t >> 5;
    int k0 = tiley * 32, n0 = tilex * 32;
    #pragma unroll
    for (int i = 0; i < 4; i++) {
        int kk = y + i * 8;
        tile[kk][x] = W[(size_t)(k0 + kk) * N + n0 + x];
    }
    __syncthreads();
    #pragma unroll
    for (int i = 0; i < 4; i++) {
        int nn = y + i * 8;
        float v = tile[x][nn];
        size_t o = (size_t)(n0 + nn) * K + k0 + x;
        split2(v, Th[o], Tl[o]);
    }
}

constexpr int PB_GA = (S_BP * S_DIN2) / 256;                 // 1536
constexpr int PB_W1 = PB_GA + (S_DIM / 32) * (S_DIN2 / 32);  // 2688
constexpr int PB_W2 = PB_W1 + (S_DIM / 32) * (S_DIM / 32);   // 3264
constexpr int PB_WP = PB_W2 + (S_EMB / 32) * (S_DIM / 32);   // 3360
constexpr int WD_ELEMS = S_VOCAB * S_EMB;                     // 3906816
constexpr int PB_WD = PB_WP + (WD_ELEMS + 1023) / 1024;       // 7176
constexpr int PB_POS = PB_WD + S_L;                           // 7196

__global__ void prep_all_kernel(const float* __restrict__ hidden,
                                const int* __restrict__ pairs,
                                const float* __restrict__ pos_emb,
                                const float* __restrict__ W1,
                                const float* __restrict__ W2,
                                const float* __restrict__ Wp,
                                const float* __restrict__ Wdec,
                                __nv_bfloat16* __restrict__ A1h, __nv_bfloat16* __restrict__ A1l,
                                __nv_bfloat16* __restrict__ W1th, __nv_bfloat16* __restrict__ W1tl,
                                __nv_bfloat16* __restrict__ W2th, __nv_bfloat16* __restrict__ W2tl,
                                __nv_bfloat16* __restrict__ Wpth, __nv_bfloat16* __restrict__ Wptl,
                                __half* __restrict__ Wdh,  __half* __restrict__ Wdl,
                                float* __restrict__ PosP) {
    int bx = blockIdx.x;
    int tid = threadIdx.x;
    if (bx < PB_GA) {
        int id = bx * 256 + tid;
        int bp = id / S_DIN2;
        int k  = id - bp * S_DIN2;
        int side = (k >= S_DIM) ? 1 : 0;
        int col  = k - side * S_DIM;
        int s = pairs[bp * 2 + side];
        int b = bp >> 5;
        float v = hidden[((size_t)(b * S_SEQ + s)) * S_DIM + col];
        split2(v, A1h[id], A1l[id]);
    } else if (bx < PB_W1) {
        int b = bx - PB_GA;
        do_transpose32(W1, S_DIN2, S_DIM, W1th, W1tl,
                       b % (S_DIM / 32), b / (S_DIM / 32));
    } else if (bx < PB_W2) {
        int b = bx - PB_W1;
        do_transpose32(W2, S_DIM, S_DIM, W2th, W2tl,
                       b % (S_DIM / 32), b / (S_DIM / 32));
    } else if (bx < PB_WP) {
        int b = bx - PB_W2;
        do_transpose32(Wp, S_DIM, S_EMB, Wpth, Wptl,
                       b % (S_EMB / 32), b / (S_EMB / 32));
    } else if (bx < PB_WD) {
        int base = (bx - PB_WP) * 1024;
        #pragma unroll
        for (int u = 0; u < 4; u++) {
            int id = base + tid + u * 256;
            if (id < WD_ELEMS) split2h(Wdec[id], Wdh[id], Wdl[id]);
        }
    } else {
        int l = bx - PB_WD;
        __shared__ float sp[S_PE];
        if (tid < S_PE) sp[tid] = pos_emb[l * S_PE + tid];
        __syncthreads();
        #pragma unroll
        for (int j = 0; j < 3; j++) {
            int n = tid + j * 256;
            float a = 0.f;
            #pragma unroll 4
            for (int k = 0; k < S_PE; k++)
                a += sp[k] * W1[(size_t)(S_DIN2 + k) * S_DIM + n];
            PosP[l * S_DIM + n] = a;
        }
    }
}

// ---------------- bf16 3-term chunk compute (GEMM1/2/3) ----------------
template<int MI>
__device__ __forceinline__ void chunk_mma(uint32_t sAh, uint32_t sAl,
                                          uint32_t sBh, uint32_t sBl,
                                          int m0, int n0, int lane,
                                          float acc[][4][4]) {
    #pragma unroll
    for (int ks = 0; ks < 4; ks++) {
        uint32_t ah[MI][4], al[MI][4], bh[8], bl[8];
        #pragma unroll
        for (int mi = 0; mi < MI; mi++) {
            int row = m0 + mi * 16 + (lane & 15);
            int c16 = ks * 2 + (lane >> 4);
            uint32_t off = swz((uint32_t)(row * 128 + c16 * 16));
            LDSM4(ah[mi], sAh + off);
            LDSM4(al[mi], sAl + off);
        }
        #pragma unroll
        for (int np = 0; np < 2; np++) {
            int row = n0 + np * 16 + ((lane >> 4) << 3) + (lane & 7);
            int c16 = ks * 2 + ((lane >> 3) & 1);
            uint32_t off = swz((uint32_t)(row * 128 + c16 * 16));
            LDSM4(&bh[np * 4], sBh + off);
            LDSM4(&bl[np * 4], sBl + off);
        }
        #pragma unroll
        for (int mi = 0; mi < MI; mi++)
            #pragma unroll
            for (int nj = 0; nj < 4; nj++) {
                MMA_BF16(acc[mi][nj], ah[mi], &bh[nj * 2]);
                MMA_BF16(acc[mi][nj], ah[mi], &bl[nj * 2]);
                MMA_BF16(acc[mi][nj], al[mi], &bh[nj * 2]);
            }
    }
}

// ---------------- fp16 2-term chunk compute (GEMM4): A single, B hi/lo ----
__device__ __forceinline__ void chunk_mma2h(uint32_t sA,
                                            uint32_t sBh, uint32_t sBl,
                                            int m0, int n0, int lane,
                                            float acc[][4][4]) {
    #pragma unroll
    for (int ks = 0; ks < 4; ks++) {
        uint32_t a[2][4], bh[8], bl[8];
        #pragma unroll
        for (int mi = 0; mi < 2; mi++) {
            int row = m0 + mi * 16 + (lane & 15);
            int c16 = ks * 2 + (lane >> 4);
            uint32_t off = swz((uint32_t)(row * 128 + c16 * 16));
            LDSM4(a[mi], sA + off);
        }
        #pragma unroll
        for (int np = 0; np < 2; np++) {
            int row = n0 + np * 16 + ((lane >> 4) << 3) + (lane & 7);
            int c16 = ks * 2 + ((lane >> 3) & 1);
            uint32_t off = swz((uint32_t)(row * 128 + c16 * 16));
            LDSM4(&bh[np * 4], sBh + off);
            LDSM4(&bl[np * 4], sBl + off);
        }
        #pragma unroll
        for (int mi = 0; mi < 2; mi++)
            #pragma unroll
            for (int nj = 0; nj < 4; nj++) {
                MMA_F16(acc[mi][nj], a[mi], &bh[nj * 2]);
                MMA_F16(acc[mi][nj], a[mi], &bl[nj * 2]);
            }
    }
}

// ---------------- k-loop GEMM: C[M,N] = A[M,K] @ Bt[N,K]^T (+bias) ----------
// Output modes: Cf != nullptr -> f32; else Cl != nullptr -> split bf16 pair;
// else Ch -> single fp16 (reinterpreted as __half*).
template<int MI>
__global__ void __launch_bounds__(256)
gemm_kl(int M, int N, int K,
        const __nv_bfloat16* __restrict__ Ahp, const __nv_bfloat16* __restrict__ Alp,
        const __nv_bfloat16* __restrict__ Bhp, const __nv_bfloat16* __restrict__ Blp,
        const float* __restrict__ bias,
        float* __restrict__ Cf,
        __nv_bfloat16* __restrict__ Ch, __nv_bfloat16* __restrict__ Cl) {
    constexpr int MT = MI * 32;
    constexpr int AB = MT * 128;            // bytes per A matrix per stage
    constexpr int SS = 2 * AB + 32768;      // stage bytes
    extern __shared__ __align__(1024) unsigned char smraw[];
    const uint32_t smb = sm_u32(smraw);
    const int tid = threadIdx.x, lane = tid & 31, warp = tid >> 5;
    const int m0 = (warp >> 2) * MI * 16, n0 = (warp & 3) * 32;
    const int am0 = blockIdx.x * MT, bn0 = blockIdx.y * 128;
    const long rowB = (long)K * 2;
    const int nch = K >> 6;

    float acc[MI][4][4];
    #pragma unroll
    for (int a = 0; a < MI; a++)
        #pragma unroll
        for (int b = 0; b < 4; b++)
            #pragma unroll
            for (int c = 0; c < 4; c++) acc[a][b][c] = 0.f;

    auto load_stage = [&](int c, int s) {
        const uint32_t sb = smb + (uint32_t)s * SS;
        constexpr int AU = AB / 16;
        #pragma unroll
        for (int i = 0; i < (2 * AU) / 256; i++) {
            int u = tid + i * 256;
            int hi = (u >= AU); int v = u - hi * AU;
            int row = v >> 3, j = v & 7;
            uint32_t off = swz((uint32_t)(row * 128 + j * 16));
            const char* src = (hi ? (const char*)Alp : (const char*)Ahp)
                              + (long)(am0 + row) * rowB + (long)c * 128 + j * 16;
            CP16(sb + (uint32_t)hi * AB + off, src, 16);
        }
        #pragma unroll
        for (int i = 0; i < 8; i++) {
            int u = tid + i * 256;
            int hi = (u >= 1024); int v = u - hi * 1024;
            int row = v >> 3, j = v & 7;
            int grow = bn0 + row;
            int ok = (grow < N) ? 16 : 0;
            uint32_t off = swz((uint32_t)(row * 128 + j * 16));
            const char* src = (hi ? (const char*)Blp : (const char*)Bhp)
                              + (long)(ok ? grow : 0) * rowB + (long)c * 128 + j * 16;
            CP16(sb + 2u * AB + (uint32_t)hi * 16384u + off, src, ok);
        }
        CP_COMMIT();
    };

    load_stage(0, 0);
    for (int c = 0; c < nch; c++) {
        int s = c & 1;
        if (c + 1 < nch) { load_stage(c + 1, s ^ 1); CP_WAIT(1); }
        else             { CP_WAIT(0); }
        __syncthreads();
        uint32_t sb = smb + (uint32_t)s * SS;
        chunk_mma<MI>(sb, sb + AB, sb + 2 * AB, sb + 2 * AB + 16384,
                      m0, n0, lane, acc);
        __syncthreads();
    }

    const int g = lane >> 2, tg = lane & 3;
    #pragma unroll
    for (int mi = 0; mi < MI; mi++) {
        int r0 = am0 + m0 + mi * 16 + g;
        size_t base0 = (size_t)r0 * N;
        size_t base1 = (size_t)(r0 + 8) * N;
        #pragma unroll
        for (int nj = 0; nj < 4; nj++) {
            int c0 = bn0 + n0 + nj * 8 + tg * 2;
            float v0 = acc[mi][nj][0], v1 = acc[mi][nj][1];
            float v2 = acc[mi][nj][2], v3 = acc[mi][nj][3];
            if (bias) {
                float bb0 = bias[c0], bb1 = bias[c0 + 1];
                v0 += bb0; v1 += bb1; v2 += bb0; v3 += bb1;
            }
            if (Cf) {
                *(float2*)(Cf + base0 + c0) = make_float2(v0, v1);
                *(float2*)(Cf + base1 + c0) = make_float2(v2, v3);
            } else if (Cl) {
                split2(v0, Ch[base0 + c0],     Cl[base0 + c0]);
                split2(v1, Ch[base0 + c0 + 1], Cl[base0 + c0 + 1]);
                split2(v2, Ch[base1 + c0],     Cl[base1 + c0]);
                split2(v3, Ch[base1 + c0 + 1], Cl[base1 + c0 + 1]);
            } else {
                __half* H = (__half*)Ch;
                H[base0 + c0]     = __float2half(v0);
                H[base0 + c0 + 1] = __float2half(v1);
                H[base1 + c0]     = __float2half(v2);
                H[base1 + c0 + 1] = __float2half(v3);
            }
        }
    }
}

// ---------------- persistent n-loop GEMM4 (K=128, fp16 2-term) -------------
// A single fp16 resident (32KB); B hi/lo double-buffered (2 x 64KB).
constexpr int NL_SMEM = 32768 + 2 * 65536;   // 163840

__global__ void __launch_bounds__(512)
gemm_nl(int M, int N,
        const __half* __restrict__ Ap,
        const __half* __restrict__ Bhp, const __half* __restrict__ Blp,
        float* __restrict__ Cf) {
    extern __shared__ __align__(1024) unsigned char smraw[];
    const uint32_t smb = sm_u32(smraw);
    const int tid = threadIdx.x, lane = tid & 31, warp = tid >> 5;
    const int m0 = (warp >> 2) * 32, n0 = (warp & 3) * 32;
    const int ntiles = (N + 127) >> 7;
    const int W = (M >> 7) * ntiles;
    const int Q = W / gridDim.x, R = W % gridDim.x;
    const int k = blockIdx.x;
    const int beg = k * Q + min(k, R);
    const int cnt = Q + (k < R ? 1 : 0);
    if (cnt == 0) return;

    auto load_A = [&](int m) {
        #pragma unroll
        for (int i = 0; i < 4; i++) {
            int u = tid + i * 512;            // [0,2048)
            int c = u >> 10; int v = u & 1023;
            int row = v >> 3, j = v & 7;
            uint32_t off = swz((uint32_t)(row * 128 + j * 16));
            const char* src = (const char*)Ap
                              + (long)(m * 128 + row) * 256 + c * 128 + j * 16;
            CP16(smb + (uint32_t)c * 16384u + off, src, 16);
        }
        CP_COMMIT();
    };
    auto load_B = [&](int n, int s) {
        #pragma unroll
        for (int i = 0; i < 8; i++) {
            int u = tid + i * 512;            // [0,4096)
            int c = u >> 11; int v = u & 2047;
            int hi = v >> 10; int v2 = v & 1023;
            int row = v2 >> 3, j = v2 & 7;
            int grow = n * 128 + row;
            int ok = (grow < N) ? 16 : 0;
            uint32_t off = swz((uint32_t)(row * 128 + j * 16));
            const char* src = (hi ? (const char*)Blp : (const char*)Bhp)
                              + (long)(ok ? grow : 0) * 256 + c * 128 + j * 16;
            CP16(smb + 32768u + (uint32_t)s * 65536u
                 + (uint32_t)c * 32768u + (uint32_t)hi * 16384u + off, src, ok);
        }
        CP_COMMIT();
    };

    int loadedm = beg / ntiles;
    load_A(loadedm);
    load_B(beg % ntiles, 0);

    const int g = lane >> 2, tg = lane & 3;
    for (int it = 0; it < cnt; it++) {
        int w = beg + it, s = it & 1;
        int mm = w / ntiles, nn = w % ntiles;
        if (mm != loadedm) { load_A(mm); loadedm = mm; }
        if (it + 1 < cnt) {
            int wn = w + 1;
            load_B(wn % ntiles, s ^ 1);
            CP_WAIT(1);
        } else {
            CP_WAIT(0);
        }
        __syncthreads();

        float acc[2][4][4];
        #pragma unroll
        for (int a = 0; a < 2; a++)
            #pragma unroll
            for (int b = 0; b < 4; b++)
                #pragma unroll
                for (int c = 0; c < 4; c++) acc[a][b][c] = 0.f;

        uint32_t bB = smb + 32768u + (uint32_t)s * 65536u;
        #pragma unroll
        for (int c = 0; c < 2; c++) {
            uint32_t aoff = smb + (uint32_t)c * 16384u;
            uint32_t boff = bB + (uint32_t)c * 32768u;
            chunk_mma2h(aoff, boff, boff + 16384u, m0, n0, lane, acc);
        }

        #pragma unroll
        for (int mi = 0; mi < 2; mi++) {
            int r0 = mm * 128 + m0 + mi * 16 + g;
            size_t base0 = (size_t)r0 * N;
            size_t base1 = (size_t)(r0 + 8) * N;
            #pragma unroll
            for (int nj = 0; nj < 4; nj++) {
                int c0 = nn * 128 + n0 + nj * 8 + tg * 2;
                if (c0 + 1 < N) {
                    *(float2*)(Cf + base0 + c0) =
                        make_float2(acc[mi][nj][0], acc[mi][nj][1]);
                    *(float2*)(Cf + base1 + c0) =
                        make_float2(acc[mi][nj][2], acc[mi][nj][3]);
                } else if (c0 < N) {
                    Cf[base0 + c0] = acc[mi][nj][0];
                    Cf[base1 + c0] = acc[mi][nj][2];
                }
            }
        }
        __syncthreads();
    }
}

// ---------------- gelu + LN (one 768-row per 256-thread block) ----------------
__device__ __forceinline__ void ln_write(float v0, float v1, float v2, int r,
                                         const float* __restrict__ gam,
                                         const float* __restrict__ bet,
                                         __nv_bfloat16* __restrict__ Hh,
                                         __nv_bfloat16* __restrict__ Hl,
                                         float* red) {
    int t = threadIdx.x;
    float s1 = v0 + v1 + v2;
    float s2 = v0 * v0 + v1 * v1 + v2 * v2;
    #pragma unroll
    for (int o = 16; o; o >>= 1) {
        s1 += __shfl_xor_sync(0xffffffffu, s1, o);
        s2 += __shfl_xor_sync(0xffffffffu, s2, o);
    }
    if ((t & 31) == 0) { red[t >> 5] = s1; red[8 + (t >> 5)] = s2; }
    __syncthreads();
    s1 = 0.f; s2 = 0.f;
    #pragma unroll
    for (int i = 0; i < 8; i++) { s1 += red[i]; s2 += red[8 + i]; }
    float mean = s1 * (1.0f / S_DIM);
    float var  = s2 * (1.0f / S_DIM) - mean * mean;
    float rstd = rsqrtf(fmaxf(var, 0.0f) + 1e-12f);
    size_t rb = (size_t)r * S_DIM;
    float v[3] = {v0, v1, v2};
    #pragma unroll
    for (int j = 0; j < 3; j++) {
        int c = t + j * 256;
        float y = (v[j] - mean) * rstd * gam[c] + bet[c];
        split2(y, Hh[rb + c], Hl[rb + c]);
    }
}

__global__ void expand_act_kernel(const float* __restrict__ P,
                                  const float* __restrict__ PosP,
                                  const float* __restrict__ b1,
                                  const float* __restrict__ g1,
                                  const float* __restrict__ be1,
                                  __nv_bfloat16* __restrict__ Hh,
                                  __nv_bfloat16* __restrict__ Hl) {
    __shared__ float red[16];
    int r = blockIdx.x;
    int bp = r / S_L, l = r - bp * S_L;
    int t = threadIdx.x;
    float v[3];
    #pragma unroll
    for (int j = 0; j < 3; j++) {
        int c = t + j * 256;
        float pre = P[bp * S_DIM + c] + PosP[l * S_DIM + c] + b1[c];
        v[j] = gelu_exact(pre);
    }
    ln_write(v[0], v[1], v[2], r, g1, be1, Hh, Hl, red);
}

__global__ void act2_kernel(const float* __restrict__ X,
                            const float* __restrict__ g2,
                            const float* __restrict__ be2,
                            __nv_bfloat16* __restrict__ Hh,
                            __nv_bfloat16* __restrict__ Hl) {
    __shared__ float red[16];
    int r = blockIdx.x;
    int t = threadIdx.x;
    size_t rb = (size_t)r * S_DIM;
    float v[3];
    #pragma unroll
    for (int j = 0; j < 3; j++) {
        int c = t + j * 256;
        v[j] = gelu_exact(X[rb + c]);
    }
    ln_write(v[0], v[1], v[2], r, g2, be2, Hh, Hl, red);
}

// ---------------- launch ----------------
extern "C" void kernel_launch(void* const* d_in, const int* in_sizes, int n_in,
                              void* d_out, int out_size) {
    (void)in_sizes; (void)n_in; (void)out_size;
    const float* hidden  = (const float*)d_in[0];
    const int*   pairs   = (const int*)d_in[1];
    const float* pos_emb = (const float*)d_in[2];
    const float* W1      = (const float*)d_in[3];
    const float* b1      = (const float*)d_in[4];
    const float* g1      = (const float*)d_in[5];
    const float* be1     = (const float*)d_in[6];
    const float* W2      = (const float*)d_in[7];
    const float* b2      = (const float*)d_in[8];
    const float* g2      = (const float*)d_in[9];
    const float* be2     = (const float*)d_in[10];
    const float* Wp      = (const float*)d_in[11];
    const float* bpv     = (const float*)d_in[12];
    const float* Wdec    = (const float*)d_in[13];
    float* out = (float*)d_out;

    void* sp = nullptr;
    cudaGetSymbolAddress(&sp, g_scratch);
    char* S = (char*)sp;
    __nv_bfloat16* A1h  = (__nv_bfloat16*)(S + OFF_A1H);
    __nv_bfloat16* A1l  = (__nv_bfloat16*)(S + OFF_A1L);
    __nv_bfloat16* W1th = (__nv_bfloat16*)(S + OFF_W1TH);
    __nv_bfloat16* W1tl = (__nv_bfloat16*)(S + OFF_W1TL);
    __nv_bfloat16* W2th = (__nv_bfloat16*)(S + OFF_W2TH);
    __nv_bfloat16* W2tl = (__nv_bfloat16*)(S + OFF_W2TL);
    __nv_bfloat16* Wpth = (__nv_bfloat16*)(S + OFF_WPTH);
    __nv_bfloat16* Wptl = (__nv_bfloat16*)(S + OFF_WPTL);
    __half* Wdh  = (__half*)(S + OFF_WDH);
    __half* Wdl  = (__half*)(S + OFF_WDL);
    float* P    = (float*)(S + OFF_P);
    float* PosP = (float*)(S + OFF_POSP);
    __nv_bfloat16* h1h = (__nv_bfloat16*)(S + OFF_H1H);
    __nv_bfloat16* h1l = (__nv_bfloat16*)(S + OFF_H1L);
    float* pre2 = (float*)(S + OFF_PRE2);
    __nv_bfloat16* h2h = (__nv_bfloat16*)(S + OFF_H2H);
    __nv_bfloat16* h2l = (__nv_bfloat16*)(S + OFF_H2L);
    __half* h3 = (__half*)(S + OFF_H3);

    constexpr int SM1 = 2 * (2 * 32 * 128 + 32768);   // MI=1: 81920
    constexpr int SM2 = 2 * (2 * 64 * 128 + 32768);   // MI=2: 98304
    cudaFuncSetAttribute(gemm_kl<1>,
                         cudaFuncAttributeMaxDynamicSharedMemorySize, SM1);
    cudaFuncSetAttribute(gemm_kl<2>,
                         cudaFuncAttributeMaxDynamicSharedMemorySize, SM2);
    cudaFuncSetAttribute(gemm_nl,
                         cudaFuncAttributeMaxDynamicSharedMemorySize, NL_SMEM);

    // 1: all prep (gather + weight transposes/splits + posmat)
    prep_all_kernel<<<PB_POS, 256>>>(hidden, pairs, pos_emb, W1, W2, Wp, Wdec,
                                     A1h, A1l, W1th, W1tl, W2th, W2tl,
                                     Wpth, Wptl, Wdh, Wdl, PosP);

    // 2: GEMM1  P[256,768] = Acat[256,1536] @ W1t^T   (48 CTAs)
    gemm_kl<1><<<dim3(S_BP / 32, S_DIM / 128), 256, SM1>>>(
        S_BP, S_DIM, S_DIN2, A1h, A1l, W1th, W1tl,
        nullptr, P, nullptr, nullptr);

    // 3: expand over L + gelu + LN1 -> h1
    expand_act_kernel<<<S_ROWS, 256>>>(P, PosP, b1, g1, be1, h1h, h1l);

    // 4: GEMM2  pre2[5120,768] = h1 @ W2t^T + b2   <-- ncu capture target
    gemm_kl<2><<<dim3(S_ROWS / 64, S_DIM / 128), 256, SM2>>>(
        S_ROWS, S_DIM, S_DIM, h1h, h1l, W2th, W2tl,
        b2, pre2, nullptr, nullptr);

    // 5: gelu + LN2 -> h2
    act2_kernel<<<S_ROWS, 256>>>(pre2, g2, be2, h2h, h2l);

    // 6: GEMM3  h3[5120,128] = h2 @ Wpt^T + bp  (single fp16 output)
    gemm_kl<2><<<dim3(S_ROWS / 64, 1), 256, SM2>>>(
        S_ROWS, S_EMB, S_DIM, h2h, h2l, Wpth, Wptl,
        bpv, nullptr, (__nv_bfloat16*)h3, nullptr);

    // 7: GEMM4  out[5120,30522] = h3 @ Wdec^T  (fp16 2-term, persistent)
    gemm_nl<<<148, 512, NL_SMEM>>>(
        S_ROWS, S_VOCAB, h3, Wdh, Wdl, out);
}